// round 1
// baseline (speedup 1.0000x reference)
#include <cuda_runtime.h>
#include <stdint.h>

// Problem geometry (fixed by reference): outputs/masks are [2,1,64,256,256]
#define HH 256
#define WW 256
#define DPT 64
#define BATCH 2
#define SLICES (BATCH * DPT)      // 128 independent 2D slices
#define WPR 8                     // 32-bit words per row (256 cols)
#define NWORDS (HH * WPR)         // 2048 words per slice bitmask
#define NPIX (HH * WW)            // 65536 pixels per slice
#define NTHREADS 512

// Per-batch accumulators: [b][0]=intersect, [b][1]=input_area, [b][2]=target_area
__device__ double g_acc[BATCH][3];

__global__ void init_acc_kernel() {
    int t = threadIdx.x;
    if (t < BATCH * 3) ((double*)g_acc)[t] = 0.0;
}

__global__ __launch_bounds__(NTHREADS, 1)
void bbsd_slice_kernel(const float* __restrict__ outp, const int* __restrict__ mskp) {
    __shared__ uint32_t mb[NWORDS];     // mask bits
    __shared__ uint32_t bufA[NWORDS];   // dilation double-buffer
    __shared__ uint32_t bufB[NWORDS];
    __shared__ float lut[32];           // weight LUT indexed by acc (0..21)
    __shared__ double red0[16], red1[16], red2[16];

    const int slice = blockIdx.x;
    const size_t base = (size_t)slice * NPIX;
    const int tid  = threadIdx.x;
    const int lane = tid & 31;
    const int wid  = tid >> 5;

    // weight LUT: dist = (22 - acc)/22, w = 2/(1+exp(10*dist))
    if (tid < 22) {
        float dist = (22.0f - (float)tid) / 22.0f;
        lut[tid] = 2.0f / (1.0f + expf(10.0f * dist));
    }

    // ---- load mask, pack to bits via ballot (fully coalesced LDG) ----
    const int* mp = mskp + base;
#pragma unroll 4
    for (int i = 0; i < NPIX / NTHREADS; i++) {
        int idx = i * NTHREADS + tid;
        unsigned bit = (mp[idx] != 0) ? 1u : 0u;
        unsigned wrd = __ballot_sync(0xffffffffu, bit);
        if (lane == 0) mb[idx >> 5] = wrd;   // idx>>5 is warp-uniform
    }
    __syncthreads();

    // thread owns half a row: 4 consecutive words
    const int row  = tid >> 1;
    const int half = tid & 1;
    const int cw0  = half * 4;            // first column-word (0 or 4)
    const int wbase = row * WPR + cw0;

    // 5-plane bit-sliced counters (acc in 0..21) held in registers
    uint32_t P0[4], P1[4], P2[4], P3[4], P4[4];

    // ---- edge map: edge = m & ~(up & down & left & right), zero-padded ----
#pragma unroll
    for (int j = 0; j < 4; j++) {
        int cw = cw0 + j;
        int gw = wbase + j;
        uint32_t m    = mb[gw];
        uint32_t up   = (row > 0)      ? mb[gw - WPR] : 0u;
        uint32_t dn   = (row < HH - 1) ? mb[gw + WPR] : 0u;
        uint32_t prev = (cw > 0)       ? mb[gw - 1]   : 0u;
        uint32_t next = (cw < WPR - 1) ? mb[gw + 1]   : 0u;
        // value of left neighbor at each bit position (bit i <-> col word*32+i)
        uint32_t lf = (m << 1) | (prev >> 31);
        uint32_t rt = (m >> 1) | (next << 31);
        uint32_t edge = m & ~(up & dn & lf & rt);
        bufA[gw] = edge;
        P0[j] = edge; P1[j] = 0u; P2[j] = 0u; P3[j] = 0u; P4[j] = 0u;  // acc += edge (round 0)
    }
    __syncthreads();

    // ---- 20 cascaded 3x3 OR-dilations, accumulate into bit-sliced counters ----
    uint32_t* src = bufA;
    uint32_t* dst = bufB;
    for (int r = 1; r <= 20; r++) {
        uint32_t va[6];
#pragma unroll
        for (int k = 0; k < 6; k++) {
            int cw = cw0 + k - 1;
            uint32_t v = 0u;
            if (cw >= 0 && cw < WPR) {
                int gw = row * WPR + cw;
                v = src[gw];
                if (row > 0)      v |= src[gw - WPR];
                if (row < HH - 1) v |= src[gw + WPR];
            }
            va[k] = v;
        }
#pragma unroll
        for (int j = 0; j < 4; j++) {
            uint32_t c = va[j + 1];
            uint32_t nw = c | (c << 1) | (va[j] >> 31) | (c >> 1) | (va[j + 2] << 31);
            dst[wbase + j] = nw;
            // ripple-carry add of nw bit into the 5-bit counter planes
            uint32_t cy = nw, t;
            t = P0[j] & cy; P0[j] ^= cy; cy = t;
            t = P1[j] & cy; P1[j] ^= cy; cy = t;
            t = P2[j] & cy; P2[j] ^= cy; cy = t;
            t = P3[j] & cy; P3[j] ^= cy; cy = t;
            P4[j] ^= cy;
        }
        __syncthreads();
        uint32_t* tmp = src; src = dst; dst = tmp;
    }

    // ---- final pass: decode acc, weight via LUT, accumulate the 3 sums ----
    float s_int = 0.f, s_ia = 0.f, s_ta = 0.f;
    const float* op = outp + base;
#pragma unroll
    for (int j = 0; j < 4; j++) {
        int gw = wbase + j;
        uint32_t mword = mb[gw];
        const float4* p4 = reinterpret_cast<const float4*>(op + (size_t)gw * 32);
#pragma unroll
        for (int q = 0; q < 8; q++) {
            float4 v = p4[q];
            float vv[4] = {v.x, v.y, v.z, v.w};
#pragma unroll
            for (int e = 0; e < 4; e++) {
                int i = q * 4 + e;
                unsigned a =  (P0[j] >> i) & 1u;
                a |= ((P1[j] >> i) & 1u) << 1;
                a |= ((P2[j] >> i) & 1u) << 2;
                a |= ((P3[j] >> i) & 1u) << 3;
                a |= ((P4[j] >> i) & 1u) << 4;
                float wgt = lut[a];
                float fm  = (float)((mword >> i) & 1u);
                float ow  = vv[e] * wgt;
                s_ia  += ow;
                s_int += ow  * fm;
                s_ta  += wgt * fm;
            }
        }
    }

    // ---- reduce: warp shuffle (double), then CTA, then one atomicAdd per sum ----
    double d0 = (double)s_int, d1 = (double)s_ia, d2 = (double)s_ta;
#pragma unroll
    for (int o = 16; o > 0; o >>= 1) {
        d0 += __shfl_down_sync(0xffffffffu, d0, o);
        d1 += __shfl_down_sync(0xffffffffu, d1, o);
        d2 += __shfl_down_sync(0xffffffffu, d2, o);
    }
    if (lane == 0) { red0[wid] = d0; red1[wid] = d1; red2[wid] = d2; }
    __syncthreads();
    if (wid == 0) {
        double a0 = (lane < 16) ? red0[lane] : 0.0;
        double a1 = (lane < 16) ? red1[lane] : 0.0;
        double a2 = (lane < 16) ? red2[lane] : 0.0;
#pragma unroll
        for (int o = 8; o > 0; o >>= 1) {
            a0 += __shfl_down_sync(0xffffffffu, a0, o);
            a1 += __shfl_down_sync(0xffffffffu, a1, o);
            a2 += __shfl_down_sync(0xffffffffu, a2, o);
        }
        if (lane == 0) {
            int b = slice >> 6;   // 64 slices per batch
            atomicAdd(&g_acc[b][0], a0);
            atomicAdd(&g_acc[b][1], a1);
            atomicAdd(&g_acc[b][2], a2);
        }
    }
}

__global__ void finalize_kernel(float* __restrict__ out) {
    if (threadIdx.x == 0) {
        double loss = 0.0;
        for (int b = 0; b < BATCH; b++) {
            double I = g_acc[b][0];
            double A = g_acc[b][1];
            double T = g_acc[b][2];
            double l = (T == 0.0) ? 0.0 : (1.0 - 2.0 * I / (A + T + 2.0e-6));
            loss += l;
        }
        out[0] = (float)(loss / (double)BATCH);
    }
}

extern "C" void kernel_launch(void* const* d_in, const int* in_sizes, int n_in,
                              void* d_out, int out_size) {
    const float* outputs = (const float*)d_in[0];  // float32 [2,1,64,256,256]
    const int*   masks   = (const int*)d_in[1];    // int32   [2,1,64,256,256]
    float* out = (float*)d_out;

    init_acc_kernel<<<1, 32>>>();
    bbsd_slice_kernel<<<SLICES, NTHREADS>>>(outputs, masks);
    finalize_kernel<<<1, 32>>>(out);
}

// round 2
// speedup vs baseline: 1.0051x; 1.0051x over previous
#include <cuda_runtime.h>
#include <stdint.h>

// Geometry fixed by the problem: outputs/masks are [2,1,64,256,256]
#define HH 256
#define WW 256
#define BATCH 2
#define SLICES 128                 // 2*64 independent 2D slices
#define WPR 8                      // 32-bit words per 256-px row
#define NWORDS (HH * WPR)          // 2048 words per slice bitmask
#define NPIX (HH * WW)             // 65536 px per slice
#define NTHREADS 512

// Per-slice partial sums: [s][0]=intersect, [s][1]=input_area, [s][2]=target_area
__device__ double g_part[SLICES][3];

__global__ __launch_bounds__(NTHREADS, 1)
void bbsd_slice_kernel(const float* __restrict__ outp, const int* __restrict__ mskp) {
    __shared__ uint32_t mb[NWORDS];            // mask bits (8 KB)
    __shared__ uint32_t buf[2][NWORDS];        // dilation double buffer (16 KB)
    __shared__ uint32_t plane[5][NWORDS / 2];  // bit-planes for one 128-row half (20 KB)
    __shared__ float lut[32];
    __shared__ double red0[16], red1[16], red2[16];

    const int slice = blockIdx.x;
    const size_t base = (size_t)slice * NPIX;
    const int tid = threadIdx.x;
    const int lane = tid & 31;
    const int wid = tid >> 5;

    // weight LUT: dist = (22 - acc)/22, w = 2/(1 + exp(10*dist)), acc in 0..21
    if (tid < 22) {
        float dist = (22.0f - (float)tid) / 22.0f;
        lut[tid] = 2.0f / (1.0f + expf(10.0f * dist));
    }

    // ---- pack mask to bits (coalesced LDG + ballot) ----
    const int* mp = mskp + base;
#pragma unroll 8
    for (int i = 0; i < NPIX / NTHREADS; i++) {
        int idx = i * NTHREADS + tid;
        unsigned wrd = __ballot_sync(0xffffffffu, mp[idx] != 0);
        if (lane == 0) mb[idx >> 5] = wrd;     // idx>>5 warp-uniform
    }
    __syncthreads();

    // thread owns half a row: 4 consecutive words
    const int row = tid >> 1;
    const int cw0 = (tid & 1) * 4;
    const int wb = row * WPR + cw0;

    // 5-plane bit-sliced per-pixel counters (acc in 0..21), register-resident
    uint32_t P0[4], P1[4], P2[4], P3[4], P4[4];

    // ---- edge: m & ~(up & down & left & right), zero padded ----
#pragma unroll
    for (int j = 0; j < 4; j++) {
        int cw = cw0 + j, gw = wb + j;
        uint32_t m  = mb[gw];
        uint32_t up = row            ? mb[gw - WPR] : 0u;
        uint32_t dn = (row < HH - 1) ? mb[gw + WPR] : 0u;
        uint32_t pv = cw             ? mb[gw - 1]   : 0u;
        uint32_t nx = (cw < WPR - 1) ? mb[gw + 1]   : 0u;
        uint32_t lf = (m << 1) | (pv >> 31);
        uint32_t rt = (m >> 1) | (nx << 31);
        uint32_t e = m & ~(up & dn & lf & rt);
        buf[0][gw] = e;
        P0[j] = e; P1[j] = 0u; P2[j] = 0u; P3[j] = 0u; P4[j] = 0u;
    }
    __syncthreads();

    // ---- cascaded 3x3 OR-dilations with saturation early-exit ----
    // Coverage is monotone: once the dilation mask is all-ones, every remaining
    // round adds exactly +1 per pixel -> fold into uniform 'extra' at decode.
    int extra = 0;
    int sb = 0;
    for (int r = 1; r <= 20; r++) {
        const uint32_t* src = buf[sb];
        uint32_t* dst = buf[sb ^ 1];
        uint32_t va[6];
#pragma unroll
        for (int k = 0; k < 6; k++) {
            int cw = cw0 + k - 1;
            uint32_t v = 0u;
            if (cw >= 0 && cw < WPR) {
                int gw = row * WPR + cw;
                v = src[gw];
                if (row)            v |= src[gw - WPR];
                if (row < HH - 1)   v |= src[gw + WPR];
            }
            va[k] = v;
        }
        uint32_t allw = 0xffffffffu;
#pragma unroll
        for (int j = 0; j < 4; j++) {
            uint32_t c = va[j + 1];
            uint32_t nw = c | (c << 1) | (va[j] >> 31) | (c >> 1) | (va[j + 2] << 31);
            dst[wb + j] = nw;
            allw &= nw;
            uint32_t cy = nw, t;                 // ripple-carry +1 where nw set
            t = P0[j] & cy; P0[j] ^= cy; cy = t;
            t = P1[j] & cy; P1[j] ^= cy; cy = t;
            t = P2[j] & cy; P2[j] ^= cy; cy = t;
            t = P3[j] & cy; P3[j] ^= cy; cy = t;
            P4[j] ^= cy;
        }
        sb ^= 1;
        // barrier + chip-wide-slice saturation test in one op
        if (__syncthreads_and(allw == 0xffffffffu)) { extra = 20 - r; break; }
    }

    // ---- decode + weighted sums, two 128-row stages, fully coalesced LDG.128 ----
    float s_ia = 0.f, s_in = 0.f, s_ta = 0.f;
    for (int half = 0; half < 2; half++) {
        __syncthreads();   // protect plane[] reuse between halves
        if ((row >> 7) == half) {
            int lw = (row & 127) * WPR + cw0;
#pragma unroll
            for (int j = 0; j < 4; j++) {
                plane[0][lw + j] = P0[j];
                plane[1][lw + j] = P1[j];
                plane[2][lw + j] = P2[j];
                plane[3][lw + j] = P3[j];
                plane[4][lw + j] = P4[j];
            }
        }
        __syncthreads();

        const float4* op4 = reinterpret_cast<const float4*>(outp + base + (size_t)half * (NPIX / 2));
        const uint32_t* mbh = mb + half * (NWORDS / 2);
#pragma unroll 4
        for (int k = 0; k < 16; k++) {
            int g = k * NTHREADS + tid;          // float4 group id; lanes consecutive
            float4 v = op4[g];
            int lw = g >> 3;
            int i0 = (g & 7) * 4;
            uint32_t q0 = plane[0][lw] >> i0;
            uint32_t q1 = plane[1][lw] >> i0;
            uint32_t q2 = plane[2][lw] >> i0;
            uint32_t q3 = plane[3][lw] >> i0;
            uint32_t q4 = plane[4][lw] >> i0;
            uint32_t qm = mbh[lw] >> i0;
            float vv[4] = {v.x, v.y, v.z, v.w};
#pragma unroll
            for (int e = 0; e < 4; e++) {
                unsigned a = ((q0 >> e) & 1u)
                           | (((q1 >> e) & 1u) << 1)
                           | (((q2 >> e) & 1u) << 2)
                           | (((q3 >> e) & 1u) << 3)
                           | (((q4 >> e) & 1u) << 4);
                float w = lut[a + extra];
                float fm = (float)((qm >> e) & 1u);
                float f = vv[e] * w;
                s_ia += f;
                s_in += f * fm;
                s_ta += w * fm;
            }
        }
    }

    // ---- reduce to per-slice partials (no atomics, no init kernel) ----
    double d0 = (double)s_in, d1 = (double)s_ia, d2 = (double)s_ta;
#pragma unroll
    for (int o = 16; o > 0; o >>= 1) {
        d0 += __shfl_down_sync(0xffffffffu, d0, o);
        d1 += __shfl_down_sync(0xffffffffu, d1, o);
        d2 += __shfl_down_sync(0xffffffffu, d2, o);
    }
    if (lane == 0) { red0[wid] = d0; red1[wid] = d1; red2[wid] = d2; }
    __syncthreads();
    if (wid == 0) {
        double a0 = (lane < 16) ? red0[lane] : 0.0;
        double a1 = (lane < 16) ? red1[lane] : 0.0;
        double a2 = (lane < 16) ? red2[lane] : 0.0;
#pragma unroll
        for (int o = 8; o > 0; o >>= 1) {
            a0 += __shfl_down_sync(0xffffffffu, a0, o);
            a1 += __shfl_down_sync(0xffffffffu, a1, o);
            a2 += __shfl_down_sync(0xffffffffu, a2, o);
        }
        if (lane == 0) {
            g_part[slice][0] = a0;
            g_part[slice][1] = a1;
            g_part[slice][2] = a2;
        }
    }
}

__global__ void finalize_kernel(float* __restrict__ out) {
    if (threadIdx.x == 0) {
        double loss = 0.0;
        for (int b = 0; b < BATCH; b++) {
            double I = 0.0, A = 0.0, T = 0.0;
            for (int s = b * 64; s < (b + 1) * 64; s++) {
                I += g_part[s][0];
                A += g_part[s][1];
                T += g_part[s][2];
            }
            loss += (T == 0.0) ? 0.0 : (1.0 - 2.0 * I / (A + T + 2.0e-6));
        }
        out[0] = (float)(loss * 0.5);  // mean over BATCH=2
    }
}

extern "C" void kernel_launch(void* const* d_in, const int* in_sizes, int n_in,
                              void* d_out, int out_size) {
    const float* outputs = (const float*)d_in[0];  // float32 [2,1,64,256,256]
    const int*   masks   = (const int*)d_in[1];    // int32   [2,1,64,256,256]
    float* out = (float*)d_out;

    bbsd_slice_kernel<<<SLICES, NTHREADS>>>(outputs, masks);
    finalize_kernel<<<1, 32>>>(out);
}

// round 3
// speedup vs baseline: 1.3324x; 1.3255x over previous
#include <cuda_runtime.h>
#include <stdint.h>

// Geometry fixed by the problem: outputs/masks are [2,1,64,256,256]
#define HH 256
#define WW 256
#define BATCH 2
#define SLICES 128                 // 2*64 independent 2D slices
#define WPR 8                      // 32-bit words per 256-px row
#define NWORDS (HH * WPR)          // 2048 words per slice bitmask
#define NPIX (HH * WW)             // 65536 px per slice
#define NTHREADS 512

// Per-slice partial sums: [s][0]=intersect, [s][1]=input_area, [s][2]=target_area
__device__ double g_part[SLICES][3];
__device__ unsigned g_ticket = 0;   // reset by the finalizing CTA each run

__global__ __launch_bounds__(NTHREADS, 1)
void bbsd_slice_kernel(const float* __restrict__ outp, const int* __restrict__ mskp,
                       float* __restrict__ out) {
    __shared__ uint32_t mb[NWORDS];            // mask bits (8 KB)
    __shared__ uint32_t buf[2][NWORDS];        // dilation double buffer (16 KB)
    __shared__ uint32_t plane[5][NWORDS / 2];  // bit-planes, one 128-row half (20 KB)
    __shared__ float lut[32];
    __shared__ double red0[16], red1[16], red2[16];
    __shared__ int s_last;

    const int slice = blockIdx.x;
    const size_t base = (size_t)slice * NPIX;
    const int tid = threadIdx.x;
    const int lane = tid & 31;
    const int wid = tid >> 5;

    // weight LUT: dist = (22 - acc)/22, w = 2/(1 + exp(10*dist)), acc in 0..21
    if (tid < 22) {
        float dist = (22.0f - (float)tid) / 22.0f;
        lut[tid] = 2.0f / (1.0f + expf(10.0f * dist));
    }

    // ---- pack mask to bits: int4 LDG.128 + nibble assembly via ballots ----
    // Each thread owns 4 consecutive pixels; 8 lanes form one 32-bit word.
    const int4* mp4 = reinterpret_cast<const int4*>(mskp + base);
#pragma unroll 4
    for (int i = 0; i < NPIX / (NTHREADS * 4); i++) {
        int g = i * NTHREADS + tid;            // int4 group id, lanes consecutive
        int4 v = mp4[g];
        unsigned nib = (v.x != 0 ? 1u : 0u) | (v.y != 0 ? 2u : 0u)
                     | (v.z != 0 ? 4u : 0u) | (v.w != 0 ? 8u : 0u);
        // build the 32-bit word for each 8-lane group via 4 ballots
        unsigned b0 = __ballot_sync(0xffffffffu, nib & 1u);
        unsigned b1 = __ballot_sync(0xffffffffu, nib & 2u);
        unsigned b2 = __ballot_sync(0xffffffffu, nib & 4u);
        unsigned b3 = __ballot_sync(0xffffffffu, nib & 8u);
        if ((lane & 7) == 0) {
            int grp = lane >> 3;               // which 8-lane group in warp
            unsigned g0 = (b0 >> (grp * 8)) & 0xffu;
            unsigned g1 = (b1 >> (grp * 8)) & 0xffu;
            unsigned g2 = (b2 >> (grp * 8)) & 0xffu;
            unsigned g3 = (b3 >> (grp * 8)) & 0xffu;
            // interleave: pixel p (0..31) = lane_in_grp*4 + comp -> bit p
            unsigned w = 0u;
#pragma unroll
            for (int q = 0; q < 8; q++) {
                w |= ((g0 >> q) & 1u) << (q * 4 + 0);
                w |= ((g1 >> q) & 1u) << (q * 4 + 1);
                w |= ((g2 >> q) & 1u) << (q * 4 + 2);
                w |= ((g3 >> q) & 1u) << (q * 4 + 3);
            }
            mb[g >> 3] = w;                    // word index = int4-group/8... g>>3
        }
    }
    __syncthreads();

    // thread owns half a row: 4 consecutive words
    const int row = tid >> 1;
    const int cw0 = (tid & 1) * 4;
    const int wb = row * WPR + cw0;

    // 5-plane bit-sliced per-pixel counters (acc in 0..21), register-resident
    uint32_t P0[4], P1[4], P2[4], P3[4], P4[4];

    // ---- edge: m & ~(up & down & left & right), zero padded ----
#pragma unroll
    for (int j = 0; j < 4; j++) {
        int cw = cw0 + j, gw = wb + j;
        uint32_t m  = mb[gw];
        uint32_t up = row            ? mb[gw - WPR] : 0u;
        uint32_t dn = (row < HH - 1) ? mb[gw + WPR] : 0u;
        uint32_t pv = cw             ? mb[gw - 1]   : 0u;
        uint32_t nx = (cw < WPR - 1) ? mb[gw + 1]   : 0u;
        uint32_t lf = (m << 1) | (pv >> 31);
        uint32_t rt = (m >> 1) | (nx << 31);
        uint32_t e = m & ~(up & dn & lf & rt);
        buf[0][gw] = e;
        P0[j] = e; P1[j] = 0u; P2[j] = 0u; P3[j] = 0u; P4[j] = 0u;
    }
    __syncthreads();

    // ---- cascaded 3x3 OR-dilations with saturation early-exit ----
    int extra = 0;
    int sb = 0;
    for (int r = 1; r <= 20; r++) {
        const uint32_t* src = buf[sb];
        uint32_t* dst = buf[sb ^ 1];
        uint32_t va[6];
#pragma unroll
        for (int k = 0; k < 6; k++) {
            int cw = cw0 + k - 1;
            uint32_t v = 0u;
            if (cw >= 0 && cw < WPR) {
                int gw = row * WPR + cw;
                v = src[gw];
                if (row)          v |= src[gw - WPR];
                if (row < HH - 1) v |= src[gw + WPR];
            }
            va[k] = v;
        }
        uint32_t allw = 0xffffffffu;
#pragma unroll
        for (int j = 0; j < 4; j++) {
            uint32_t c = va[j + 1];
            uint32_t nw = c | (c << 1) | (va[j] >> 31) | (c >> 1) | (va[j + 2] << 31);
            dst[wb + j] = nw;
            allw &= nw;
            uint32_t cy = nw, t;               // ripple-carry +1 where nw set
            t = P0[j] & cy; P0[j] ^= cy; cy = t;
            t = P1[j] & cy; P1[j] ^= cy; cy = t;
            t = P2[j] & cy; P2[j] ^= cy; cy = t;
            t = P3[j] & cy; P3[j] ^= cy; cy = t;
            P4[j] ^= cy;
        }
        sb ^= 1;
        if (__syncthreads_and(allw == 0xffffffffu)) { extra = 20 - r; break; }
    }

    // ---- decode + weighted sums, two 128-row stages, coalesced LDG.128 ----
    float s_ia = 0.f, s_in = 0.f, s_ta = 0.f;
    for (int half = 0; half < 2; half++) {
        __syncthreads();
        if ((row >> 7) == half) {
            int lw = (row & 127) * WPR + cw0;
#pragma unroll
            for (int j = 0; j < 4; j++) {
                plane[0][lw + j] = P0[j];
                plane[1][lw + j] = P1[j];
                plane[2][lw + j] = P2[j];
                plane[3][lw + j] = P3[j];
                plane[4][lw + j] = P4[j];
            }
        }
        __syncthreads();

        const float4* op4 = reinterpret_cast<const float4*>(outp + base + (size_t)half * (NPIX / 2));
        const uint32_t* mbh = mb + half * (NWORDS / 2);
#pragma unroll 4
        for (int k = 0; k < 16; k++) {
            int g = k * NTHREADS + tid;
            float4 v = op4[g];
            int lw = g >> 3;
            int i0 = (g & 7) * 4;
            uint32_t q0 = plane[0][lw] >> i0;
            uint32_t q1 = plane[1][lw] >> i0;
            uint32_t q2 = plane[2][lw] >> i0;
            uint32_t q3 = plane[3][lw] >> i0;
            uint32_t q4 = plane[4][lw] >> i0;
            uint32_t qm = mbh[lw] >> i0;
            float vv[4] = {v.x, v.y, v.z, v.w};
#pragma unroll
            for (int e = 0; e < 4; e++) {
                unsigned a = ((q0 >> e) & 1u)
                           | (((q1 >> e) & 1u) << 1)
                           | (((q2 >> e) & 1u) << 2)
                           | (((q3 >> e) & 1u) << 3)
                           | (((q4 >> e) & 1u) << 4);
                float w = lut[a + extra];
                float fm = (float)((qm >> e) & 1u);
                float f = vv[e] * w;
                s_ia += f;
                s_in += f * fm;
                s_ta += w * fm;
            }
        }
    }

    // ---- reduce to per-slice partials ----
    double d0 = (double)s_in, d1 = (double)s_ia, d2 = (double)s_ta;
#pragma unroll
    for (int o = 16; o > 0; o >>= 1) {
        d0 += __shfl_down_sync(0xffffffffu, d0, o);
        d1 += __shfl_down_sync(0xffffffffu, d1, o);
        d2 += __shfl_down_sync(0xffffffffu, d2, o);
    }
    if (lane == 0) { red0[wid] = d0; red1[wid] = d1; red2[wid] = d2; }
    __syncthreads();
    if (wid == 0) {
        double a0 = (lane < 16) ? red0[lane] : 0.0;
        double a1 = (lane < 16) ? red1[lane] : 0.0;
        double a2 = (lane < 16) ? red2[lane] : 0.0;
#pragma unroll
        for (int o = 8; o > 0; o >>= 1) {
            a0 += __shfl_down_sync(0xffffffffu, a0, o);
            a1 += __shfl_down_sync(0xffffffffu, a1, o);
            a2 += __shfl_down_sync(0xffffffffu, a2, o);
        }
        if (lane == 0) {
            g_part[slice][0] = a0;
            g_part[slice][1] = a1;
            g_part[slice][2] = a2;
        }
    }

    // ---- fused finalize: last-arriving CTA computes the scalar loss ----
    if (tid == 0) {
        __threadfence();                              // publish g_part writes
        unsigned t = atomicAdd(&g_ticket, 1u);
        s_last = (t == SLICES - 1);
    }
    __syncthreads();
    if (s_last && wid == 0) {
        __threadfence();                              // see all g_part writes
        double loss = 0.0;
#pragma unroll
        for (int b = 0; b < BATCH; b++) {
            // 64 slices per batch: lane covers 2, then warp-reduce
            double i0 = g_part[b * 64 + lane][0] + g_part[b * 64 + 32 + lane][0];
            double a0 = g_part[b * 64 + lane][1] + g_part[b * 64 + 32 + lane][1];
            double t0 = g_part[b * 64 + lane][2] + g_part[b * 64 + 32 + lane][2];
#pragma unroll
            for (int o = 16; o > 0; o >>= 1) {
                i0 += __shfl_down_sync(0xffffffffu, i0, o);
                a0 += __shfl_down_sync(0xffffffffu, a0, o);
                t0 += __shfl_down_sync(0xffffffffu, t0, o);
            }
            if (lane == 0)
                loss += (t0 == 0.0) ? 0.0 : (1.0 - 2.0 * i0 / (a0 + t0 + 2.0e-6));
        }
        if (lane == 0) {
            out[0] = (float)(loss * 0.5);             // mean over BATCH=2
            g_ticket = 0;                             // reset for next graph replay
        }
    }
}

extern "C" void kernel_launch(void* const* d_in, const int* in_sizes, int n_in,
                              void* d_out, int out_size) {
    const float* outputs = (const float*)d_in[0];  // float32 [2,1,64,256,256]
    const int*   masks   = (const int*)d_in[1];    // int32   [2,1,64,256,256]
    float* out = (float*)d_out;

    bbsd_slice_kernel<<<SLICES, NTHREADS>>>(outputs, masks, out);
}

// round 4
// speedup vs baseline: 1.3906x; 1.0437x over previous
#include <cuda_runtime.h>
#include <stdint.h>

// Geometry fixed by the problem: outputs/masks are [2,1,64,256,256]
#define HH 256
#define WW 256
#define BATCH 2
#define SLICES 128                 // 2*64 independent 2D slices
#define WPR 8                      // 32-bit words per 256-px row
#define NWORDS (HH * WPR)          // 2048 words per slice bitmask
#define NPIX (HH * WW)             // 65536 px per slice
#define NTHREADS 512

// Per-slice partial sums: [s][0]=intersect, [s][1]=input_area, [s][2]=target_area
__device__ double g_part[SLICES][3];
__device__ unsigned g_ticket = 0;   // reset by the finalizing CTA each run

__global__ __launch_bounds__(NTHREADS, 1)
void bbsd_slice_kernel(const float* __restrict__ outp, const int* __restrict__ mskp,
                       float* __restrict__ out) {
    __shared__ uint32_t mb[NWORDS];            // mask bits (8 KB)
    __shared__ uint32_t buf[2][NWORDS];        // dilation double buffer (16 KB)
    __shared__ uint32_t plane[5][NWORDS / 2];  // bit-planes, one 128-row half (20 KB)
    __shared__ float lut[64];
    __shared__ double red0[16], red1[16], red2[16];
    __shared__ int s_last;

    const int slice = blockIdx.x;
    const size_t base = (size_t)slice * NPIX;
    const int tid = threadIdx.x;
    const int lane = tid & 31;
    const int wid = tid >> 5;

    // weight LUT: dist = (22 - acc)/22, w = 2/(1 + exp(10*dist)), acc in 0..21
    // padded to 64 entries so fast-path index a+extra never needs clamping
    if (tid < 64) {
        int a = tid < 22 ? tid : 21;
        float dist = (22.0f - (float)a) / 22.0f;
        lut[tid] = 2.0f / (1.0f + expf(10.0f * dist));
    }

    // ---- pack mask to bits: scalar coalesced LDG + ballot (4 instrs/iter) ----
    const int* mp = mskp + base;
#pragma unroll 8
    for (int i = 0; i < NPIX / NTHREADS; i++) {
        int idx = i * NTHREADS + tid;
        unsigned wrd = __ballot_sync(0xffffffffu, mp[idx] != 0);
        if (lane == 0) mb[idx >> 5] = wrd;     // idx>>5 warp-uniform
    }
    __syncthreads();

    // thread owns half a row: 4 consecutive words
    const int row = tid >> 1;
    const int cw0 = (tid & 1) * 4;
    const int wb = row * WPR + cw0;

    // 5-plane bit-sliced per-pixel counters (acc in 0..21), register-resident
    uint32_t P0[4], P1[4], P2[4], P3[4], P4[4];

    // ---- edge: m & ~(up & down & left & right), zero padded ----
#pragma unroll
    for (int j = 0; j < 4; j++) {
        int cw = cw0 + j, gw = wb + j;
        uint32_t m  = mb[gw];
        uint32_t up = row            ? mb[gw - WPR] : 0u;
        uint32_t dn = (row < HH - 1) ? mb[gw + WPR] : 0u;
        uint32_t pv = cw             ? mb[gw - 1]   : 0u;
        uint32_t nx = (cw < WPR - 1) ? mb[gw + 1]   : 0u;
        uint32_t lf = (m << 1) | (pv >> 31);
        uint32_t rt = (m >> 1) | (nx << 31);
        uint32_t e = m & ~(up & dn & lf & rt);
        buf[0][gw] = e;
        P0[j] = e; P1[j] = 0u; P2[j] = 0u; P3[j] = 0u; P4[j] = 0u;
    }
    __syncthreads();

    // ---- cascaded 3x3 OR-dilations with saturation early-exit ----
    // Once the dilation mask is all-ones every remaining round adds +1 uniformly
    // -> fold into 'extra' applied at LUT-lookup time.
    int extra = 0;
    int sb = 0;
    for (int r = 1; r <= 20; r++) {
        const uint32_t* src = buf[sb];
        uint32_t* dst = buf[sb ^ 1];
        uint32_t va[6];
#pragma unroll
        for (int k = 0; k < 6; k++) {
            int cw = cw0 + k - 1;
            uint32_t v = 0u;
            if (cw >= 0 && cw < WPR) {
                int gw = row * WPR + cw;
                v = src[gw];
                if (row)          v |= src[gw - WPR];
                if (row < HH - 1) v |= src[gw + WPR];
            }
            va[k] = v;
        }
        uint32_t allw = 0xffffffffu;
#pragma unroll
        for (int j = 0; j < 4; j++) {
            uint32_t c = va[j + 1];
            uint32_t nw = c | (c << 1) | (va[j] >> 31) | (c >> 1) | (va[j + 2] << 31);
            dst[wb + j] = nw;
            allw &= nw;
            uint32_t cy = nw, t;               // ripple-carry +1 where nw set
            t = P0[j] & cy; P0[j] ^= cy; cy = t;
            t = P1[j] & cy; P1[j] ^= cy; cy = t;
            t = P2[j] & cy; P2[j] ^= cy; cy = t;
            t = P3[j] & cy; P3[j] ^= cy; cy = t;
            P4[j] ^= cy;
        }
        sb ^= 1;
        if (__syncthreads_and(allw == 0xffffffffu)) { extra = 20 - r; break; }
    }

    // ---- decode + weighted sums, two 128-row stages, coalesced LDG.128 ----
    float s_ia = 0.f, s_in = 0.f, s_ta = 0.f;
    for (int half = 0; half < 2; half++) {
        __syncthreads();
        if ((row >> 7) == half) {
            int lw = (row & 127) * WPR + cw0;
#pragma unroll
            for (int j = 0; j < 4; j++) {
                plane[0][lw + j] = P0[j];
                plane[1][lw + j] = P1[j];
                plane[2][lw + j] = P2[j];
                plane[3][lw + j] = P3[j];
                plane[4][lw + j] = P4[j];
            }
        }
        __syncthreads();

        const float4* op4 = reinterpret_cast<const float4*>(outp + base + (size_t)half * (NPIX / 2));
        const uint32_t* mbh = mb + half * (NWORDS / 2);
#pragma unroll 4
        for (int k = 0; k < 16; k++) {
            int g = k * NTHREADS + tid;        // float4 group; lanes consecutive
            float4 v = op4[g];
            int lw = g >> 3;
            int i0 = (g & 7) * 4;
            uint32_t p0 = plane[0][lw];
            uint32_t p1 = plane[1][lw];
            uint32_t p2 = plane[2][lw];
            uint32_t p3 = plane[3][lw];
            uint32_t p4 = plane[4][lw];
            uint32_t qm = mbh[lw] >> i0;
            float vv[4] = {v.x, v.y, v.z, v.w};

            // fast path: all 32 px in this word share one acc value
            bool uni = ((p0 + 1u) <= 1u) & ((p1 + 1u) <= 1u) & ((p2 + 1u) <= 1u)
                     & ((p3 + 1u) <= 1u) & ((p4 + 1u) <= 1u);
            if (uni) {
                unsigned a = (p0 & 1u) | ((p1 & 1u) << 1) | ((p2 & 1u) << 2)
                           | ((p3 & 1u) << 3) | ((p4 & 1u) << 4);
                float w = lut[a + extra];
                float acc4 = 0.f, accm = 0.f;
#pragma unroll
                for (int e = 0; e < 4; e++) {
                    acc4 += vv[e];
                    accm += ((qm >> e) & 1u) ? vv[e] : 0.f;
                }
                s_ia += w * acc4;
                s_in += w * accm;
                s_ta += w * (float)__popc(qm & 0xFu);
            } else {
                uint32_t q0 = p0 >> i0, q1 = p1 >> i0, q2 = p2 >> i0,
                         q3 = p3 >> i0, q4 = p4 >> i0;
#pragma unroll
                for (int e = 0; e < 4; e++) {
                    unsigned a = ((q0 >> e) & 1u)
                               | (((q1 >> e) & 1u) << 1)
                               | (((q2 >> e) & 1u) << 2)
                               | (((q3 >> e) & 1u) << 3)
                               | (((q4 >> e) & 1u) << 4);
                    float w = lut[a + extra];
                    float fm = (float)((qm >> e) & 1u);
                    float f = vv[e] * w;
                    s_ia += f;
                    s_in += f * fm;
                    s_ta += w * fm;
                }
            }
        }
    }

    // ---- reduce to per-slice partials ----
    double d0 = (double)s_in, d1 = (double)s_ia, d2 = (double)s_ta;
#pragma unroll
    for (int o = 16; o > 0; o >>= 1) {
        d0 += __shfl_down_sync(0xffffffffu, d0, o);
        d1 += __shfl_down_sync(0xffffffffu, d1, o);
        d2 += __shfl_down_sync(0xffffffffu, d2, o);
    }
    if (lane == 0) { red0[wid] = d0; red1[wid] = d1; red2[wid] = d2; }
    __syncthreads();
    if (wid == 0) {
        double a0 = (lane < 16) ? red0[lane] : 0.0;
        double a1 = (lane < 16) ? red1[lane] : 0.0;
        double a2 = (lane < 16) ? red2[lane] : 0.0;
#pragma unroll
        for (int o = 8; o > 0; o >>= 1) {
            a0 += __shfl_down_sync(0xffffffffu, a0, o);
            a1 += __shfl_down_sync(0xffffffffu, a1, o);
            a2 += __shfl_down_sync(0xffffffffu, a2, o);
        }
        if (lane == 0) {
            g_part[slice][0] = a0;
            g_part[slice][1] = a1;
            g_part[slice][2] = a2;
        }
    }

    // ---- fused finalize: last-arriving CTA computes the scalar loss ----
    if (tid == 0) {
        __threadfence();                              // publish g_part writes
        unsigned t = atomicAdd(&g_ticket, 1u);
        s_last = (t == SLICES - 1);
    }
    __syncthreads();
    if (s_last && wid == 0) {
        __threadfence();                              // see all g_part writes
        double loss = 0.0;
#pragma unroll
        for (int b = 0; b < BATCH; b++) {
            double i0 = g_part[b * 64 + lane][0] + g_part[b * 64 + 32 + lane][0];
            double a0 = g_part[b * 64 + lane][1] + g_part[b * 64 + 32 + lane][1];
            double t0 = g_part[b * 64 + lane][2] + g_part[b * 64 + 32 + lane][2];
#pragma unroll
            for (int o = 16; o > 0; o >>= 1) {
                i0 += __shfl_down_sync(0xffffffffu, i0, o);
                a0 += __shfl_down_sync(0xffffffffu, a0, o);
                t0 += __shfl_down_sync(0xffffffffu, t0, o);
            }
            if (lane == 0)
                loss += (t0 == 0.0) ? 0.0 : (1.0 - 2.0 * i0 / (a0 + t0 + 2.0e-6));
        }
        if (lane == 0) {
            out[0] = (float)(loss * 0.5);             // mean over BATCH=2
            g_ticket = 0;                             // reset for next graph replay
        }
    }
}

extern "C" void kernel_launch(void* const* d_in, const int* in_sizes, int n_in,
                              void* d_out, int out_size) {
    const float* outputs = (const float*)d_in[0];  // float32 [2,1,64,256,256]
    const int*   masks   = (const int*)d_in[1];    // int32   [2,1,64,256,256]
    float* out = (float*)d_out;

    bbsd_slice_kernel<<<SLICES, NTHREADS>>>(outputs, masks, out);
}